// round 5
// baseline (speedup 1.0000x reference)
#include <cuda_runtime.h>
#include <cuda_bf16.h>
#include <cstdint>

#define T_SEQ 4096
#define C_DIM 1024
#define QKV_DIM 3072
#define NHEAD 16
#define DHEAD 64

// ---------------------------------------------------------------------------
// Static device scratch (no allocations allowed)
// ---------------------------------------------------------------------------
__device__ __nv_bfloat16 g_xh[T_SEQ * C_DIM];
__device__ __nv_bfloat16 g_xl[T_SEQ * C_DIM];
__device__ __nv_bfloat16 g_Wh[QKV_DIM * C_DIM];   // [Wq;Wk;Wv] hi
__device__ __nv_bfloat16 g_Wl[QKV_DIM * C_DIM];   // [Wq;Wk;Wv] lo
__device__ __nv_bfloat16 g_Wph[C_DIM * C_DIM];
__device__ __nv_bfloat16 g_Wpl[C_DIM * C_DIM];
__device__ float         g_bqkv[QKV_DIM];
__device__ __nv_bfloat16 g_qkvh[T_SEQ * QKV_DIM]; // fused q|k|v hi (q pre-scaled)
__device__ __nv_bfloat16 g_qkvl[T_SEQ * QKV_DIM]; // fused q|k|v lo
__device__ __nv_bfloat16 g_yh[T_SEQ * C_DIM];
__device__ __nv_bfloat16 g_yl[T_SEQ * C_DIM];

// ---------------------------------------------------------------------------
// PTX helpers (arch-agnostic; no tcgen05 — harness PTX target rejects it)
// ---------------------------------------------------------------------------
__device__ __forceinline__ uint32_t smem_u32(const void* p) {
    uint32_t a;
    asm("{ .reg .u64 t; cvta.to.shared.u64 t, %1; cvt.u32.u64 %0, t; }"
        : "=r"(a) : "l"(p));
    return a;
}
__device__ __forceinline__ void cp16(uint32_t dst, const void* src) {
    asm volatile("cp.async.cg.shared.global [%0], [%1], 16;" :: "r"(dst), "l"(src));
}
__device__ __forceinline__ void cp_commit() {
    asm volatile("cp.async.commit_group;" ::: "memory");
}
__device__ __forceinline__ void cp_wait0() {
    asm volatile("cp.async.wait_group 0;" ::: "memory");
}
__device__ __forceinline__ void cp_wait1() {
    asm volatile("cp.async.wait_group 1;" ::: "memory");
}
__device__ __forceinline__ void ldsm4(uint32_t* r, uint32_t addr) {
    asm volatile("ldmatrix.sync.aligned.m8n8.x4.shared.b16 {%0,%1,%2,%3}, [%4];"
                 : "=r"(r[0]), "=r"(r[1]), "=r"(r[2]), "=r"(r[3]) : "r"(addr));
}
__device__ __forceinline__ void ldsm2(uint32_t* r, uint32_t addr) {
    asm volatile("ldmatrix.sync.aligned.m8n8.x2.shared.b16 {%0,%1}, [%2];"
                 : "=r"(r[0]), "=r"(r[1]) : "r"(addr));
}
__device__ __forceinline__ void ldsm2t(uint32_t* r, uint32_t addr) {
    asm volatile("ldmatrix.sync.aligned.m8n8.x2.trans.shared.b16 {%0,%1}, [%2];"
                 : "=r"(r[0]), "=r"(r[1]) : "r"(addr));
}
__device__ __forceinline__ void mma16816(float* c, const uint32_t* a, const uint32_t* b) {
    asm volatile(
        "mma.sync.aligned.m16n8k16.row.col.f32.bf16.bf16.f32 "
        "{%0,%1,%2,%3}, {%4,%5,%6,%7}, {%8,%9}, {%0,%1,%2,%3};"
        : "+f"(c[0]), "+f"(c[1]), "+f"(c[2]), "+f"(c[3])
        : "r"(a[0]), "r"(a[1]), "r"(a[2]), "r"(a[3]), "r"(b[0]), "r"(b[1]));
}
__device__ __forceinline__ uint32_t packbf(float a, float b) {
    __nv_bfloat162 t = __floats2bfloat162_rn(a, b);
    return *(uint32_t*)&t;
}

#define SW128(o) ((o) ^ (((o) >> 3) & 0x70))

// ---------------------------------------------------------------------------
// Splits: fp32 -> bf16 hi + bf16 lo
// ---------------------------------------------------------------------------
__device__ __forceinline__ void split4(float4 v, __nv_bfloat162* h, __nv_bfloat162* l,
                                       int i)
{
    __nv_bfloat16 h0 = __float2bfloat16(v.x);
    __nv_bfloat16 h1 = __float2bfloat16(v.y);
    __nv_bfloat16 h2 = __float2bfloat16(v.z);
    __nv_bfloat16 h3 = __float2bfloat16(v.w);
    __nv_bfloat16 l0 = __float2bfloat16(v.x - __bfloat162float(h0));
    __nv_bfloat16 l1 = __float2bfloat16(v.y - __bfloat162float(h1));
    __nv_bfloat16 l2 = __float2bfloat16(v.z - __bfloat162float(h2));
    __nv_bfloat16 l3 = __float2bfloat16(v.w - __bfloat162float(h3));
    h[i * 2]     = __halves2bfloat162(h0, h1);
    h[i * 2 + 1] = __halves2bfloat162(h2, h3);
    l[i * 2]     = __halves2bfloat162(l0, l1);
    l[i * 2 + 1] = __halves2bfloat162(l2, l3);
}

__global__ void split_kernel(const float4* __restrict__ src,
                             __nv_bfloat162* __restrict__ h,
                             __nv_bfloat162* __restrict__ l, int n4)
{
    int i = blockIdx.x * blockDim.x + threadIdx.x;
    if (i >= n4) return;
    split4(src[i], h, l, i);
}

// All four weight matrices in one launch. 4096 blocks of 256: 1024 per matrix.
__global__ void split_w4(const float4* __restrict__ Wq, const float4* __restrict__ Wk,
                         const float4* __restrict__ Wv, const float4* __restrict__ Wp,
                         __nv_bfloat162* __restrict__ Wh, __nv_bfloat162* __restrict__ Wl,
                         __nv_bfloat162* __restrict__ Wph, __nv_bfloat162* __restrict__ Wpl)
{
    int w = blockIdx.x >> 10;                       // 0..3
    int i = (blockIdx.x & 1023) * blockDim.x + threadIdx.x;   // 0..262143
    const float4* src = (w == 0) ? Wq : (w == 1) ? Wk : (w == 2) ? Wv : Wp;
    __nv_bfloat162* h = (w == 3) ? Wph : Wh + (size_t)w * 524288;
    __nv_bfloat162* l = (w == 3) ? Wpl : Wl + (size_t)w * 524288;
    split4(src[i], h, l, i);
}

__global__ void concat_bias(const float* __restrict__ bq, const float* __restrict__ bk,
                            const float* __restrict__ bv, float* __restrict__ dst)
{
    int i = blockIdx.x * blockDim.x + threadIdx.x;
    if (i < 1024)      dst[i] = bq[i];
    else if (i < 2048) dst[i] = bk[i - 1024];
    else               dst[i] = bv[i - 2048];
}

// ---------------------------------------------------------------------------
// mma.sync split-bf16 GEMM (NT): C = (Ah+Al) @ (Bh+Bl)^T + bias
// 128x128 tile, BK=64, 256 threads, 3-stage cp.async pipeline (192KB smem).
// mode 0: fp32 C.  mode 1: split-bf16 Ch/Cl, 0.125 scale on cols < C_DIM.
// ---------------------------------------------------------------------------
#define GEMM_SMEM (3 * 4 * 16384)

__global__ __launch_bounds__(256, 1)
void gemm_bf16s(const __nv_bfloat16* __restrict__ Ah, const __nv_bfloat16* __restrict__ Al,
                const __nv_bfloat16* __restrict__ Bh, const __nv_bfloat16* __restrict__ Bl,
                const float* __restrict__ bias, float* __restrict__ C,
                __nv_bfloat16* __restrict__ Ch, __nv_bfloat16* __restrict__ Cl,
                int N, int K, int mode)
{
    extern __shared__ char smem[];
    const int tid  = threadIdx.x;
    const int warp = tid >> 5;
    const int lane = tid & 31;
    const int wm   = warp >> 2;
    const int wn   = warp & 3;
    const int m0   = blockIdx.y * 128;
    const int n0   = blockIdx.x * 128;
    const uint32_t sbase = smem_u32(smem);
    const int NC = K / 64;   // 16

    const int lrow = tid >> 1;
    const int lj0  = (tid & 1) * 4;

    auto load_stage = [&](int c, int s) {
        const uint32_t sb = sbase + s * 65536;
        const size_t ka = (size_t)(m0 + lrow) * K + c * 64;
        const size_t kb = (size_t)(n0 + lrow) * K + c * 64;
#pragma unroll
        for (int j = lj0; j < lj0 + 4; j++) {
            uint32_t sw = SW128(lrow * 128 + j * 16);
            cp16(sb + sw,         Ah + ka + j * 8);
            cp16(sb + 16384 + sw, Al + ka + j * 8);
            cp16(sb + 32768 + sw, Bh + kb + j * 8);
            cp16(sb + 49152 + sw, Bl + kb + j * 8);
        }
        cp_commit();
    };

    float acc[4][4][4];
#pragma unroll
    for (int i = 0; i < 4; i++)
#pragma unroll
        for (int j = 0; j < 4; j++)
#pragma unroll
            for (int q = 0; q < 4; q++) acc[i][j][q] = 0.f;

    const int alr = lane & 15;
    const int alk = (lane >> 4) & 1;
    const int bro = lane & 7;
    const int bk_ = (lane >> 3) & 1;

    load_stage(0, 0);
    load_stage(1, 1);

    for (int c = 0; c < NC; c++) {
        if (c < NC - 1) cp_wait1(); else cp_wait0();
        __syncthreads();
        if (c + 2 < NC) load_stage(c + 2, (c + 2) % 3);

        const uint32_t sb = sbase + (c % 3) * 65536;
#pragma unroll
        for (int kk = 0; kk < 4; kk++) {
            uint32_t ah[4][4], al4[4][4], bh[4][2], bl4[4][2];
#pragma unroll
            for (int mi = 0; mi < 4; mi++) {
                uint32_t off = SW128((wm * 64 + mi * 16 + alr) * 128 + kk * 32 + alk * 16);
                ldsm4(ah[mi],  sb + off);
                ldsm4(al4[mi], sb + 16384 + off);
            }
#pragma unroll
            for (int ni = 0; ni < 4; ni++) {
                uint32_t off = SW128((wn * 32 + ni * 8 + bro) * 128 + kk * 32 + bk_ * 16);
                ldsm2(bh[ni],  sb + 32768 + off);
                ldsm2(bl4[ni], sb + 49152 + off);
            }
#pragma unroll
            for (int mi = 0; mi < 4; mi++)
#pragma unroll
                for (int ni = 0; ni < 4; ni++) {
                    mma16816(acc[mi][ni], ah[mi],  bh[ni]);
                    mma16816(acc[mi][ni], ah[mi],  bl4[ni]);
                    mma16816(acc[mi][ni], al4[mi], bh[ni]);
                }
        }
    }

    const int g   = lane >> 2;
    const int tig = lane & 3;
#pragma unroll
    for (int mi = 0; mi < 4; mi++) {
#pragma unroll
        for (int ni = 0; ni < 4; ni++) {
            int row = m0 + wm * 64 + mi * 16 + g;
            int col = n0 + wn * 32 + ni * 8 + tig * 2;
            float b0 = bias[col], b1 = bias[col + 1];
            if (mode == 0) {
                float2 v0 = {acc[mi][ni][0] + b0, acc[mi][ni][1] + b1};
                float2 v1 = {acc[mi][ni][2] + b0, acc[mi][ni][3] + b1};
                *(float2*)(C + (size_t)row * N + col)       = v0;
                *(float2*)(C + (size_t)(row + 8) * N + col) = v1;
            } else {
                float sc = (col < C_DIM) ? 0.125f : 1.0f;   // softmax scale on q
                float v00 = (acc[mi][ni][0] + b0) * sc;
                float v01 = (acc[mi][ni][1] + b1) * sc;
                float v10 = (acc[mi][ni][2] + b0) * sc;
                float v11 = (acc[mi][ni][3] + b1) * sc;
                __nv_bfloat162 h0 = __floats2bfloat162_rn(v00, v01);
                __nv_bfloat162 h1 = __floats2bfloat162_rn(v10, v11);
                __nv_bfloat162 l0 = __floats2bfloat162_rn(v00 - __low2float(h0),
                                                          v01 - __high2float(h0));
                __nv_bfloat162 l1 = __floats2bfloat162_rn(v10 - __low2float(h1),
                                                          v11 - __high2float(h1));
                *(__nv_bfloat162*)(Ch + (size_t)row * N + col)       = h0;
                *(__nv_bfloat162*)(Ch + (size_t)(row + 8) * N + col) = h1;
                *(__nv_bfloat162*)(Cl + (size_t)row * N + col)       = l0;
                *(__nv_bfloat162*)(Cl + (size_t)(row + 8) * N + col) = l1;
            }
        }
    }
}

// ---------------------------------------------------------------------------
// Flash attention via mma.sync, split-bf16. CTA = 128 queries x 1 head,
// 8 warps (16 q-rows each), 256 threads. K/V tile = 64 keys, 2-stage cp.async.
// SMEM: qh|ql 32KB + 2 stages x {kh,kl,vh,vl} 32KB = 96KB; 2 CTAs/SM.
// ---------------------------------------------------------------------------
#define ATTN_SMEM (32768 + 2 * 32768)

__global__ __launch_bounds__(256, 2)
void attn_mma(const __nv_bfloat16* __restrict__ qkvh,
              const __nv_bfloat16* __restrict__ qkvl,
              __nv_bfloat16* __restrict__ Yh, __nv_bfloat16* __restrict__ Yl)
{
    extern __shared__ char smem[];
    const uint32_t sb = smem_u32(smem);
    const int qb   = gridDim.x - 1 - blockIdx.x;   // heavy blocks first
    const int h    = blockIdx.y;
    const int tid  = threadIdx.x;
    const int warp = tid >> 5;
    const int lane = tid & 31;
    const int g    = lane >> 2;
    const int quad = lane & 3;
    const int nkb  = 2 * qb + 2;                   // k-blocks to process

    // Q (hi/lo) -> smem [0, 32768)
    {
        const int lr  = tid >> 1;                  // 0..127
        const int lj0 = (tid & 1) * 4;
        const size_t base = (size_t)(qb * 128 + lr) * QKV_DIM + h * DHEAD;
#pragma unroll
        for (int j = lj0; j < lj0 + 4; j++) {
            uint32_t sw = SW128(lr * 128 + j * 16);
            cp16(sb + sw,         qkvh + base + j * 8);
            cp16(sb + 16384 + sw, qkvl + base + j * 8);
        }
    }
    const int lrv = tid >> 2;                      // 0..63
    const int ljv = (tid & 3) * 2;
    auto load_kv = [&](int kb, int s) {
        const uint32_t b = sb + 32768 + s * 32768;
        const size_t kbase = (size_t)(kb * 64 + lrv) * QKV_DIM + C_DIM + h * DHEAD;
        const size_t vbase = kbase + C_DIM;
#pragma unroll
        for (int j = ljv; j < ljv + 2; j++) {
            uint32_t sw = SW128(lrv * 128 + j * 16);
            cp16(b + sw,         qkvh + kbase + j * 8);
            cp16(b + 8192 + sw,  qkvl + kbase + j * 8);
            cp16(b + 16384 + sw, qkvh + vbase + j * 8);
            cp16(b + 24576 + sw, qkvl + vbase + j * 8);
        }
        cp_commit();
    };
    load_kv(0, 0);   // Q copies ride in this group

    float oacc[8][4];
#pragma unroll
    for (int i = 0; i < 8; i++)
#pragma unroll
        for (int j = 0; j < 4; j++) oacc[i][j] = 0.f;
    float mr0 = -1e30f, mr1 = -1e30f, lr0 = 0.f, lr1 = 0.f;

    const int alr = lane & 15;
    const int alk = (lane >> 4) & 1;
    const int bro = lane & 7;
    const int bk_ = (lane >> 3) & 1;

    for (int kb = 0; kb < nkb; kb++) {
        const int s = kb & 1;
        if (kb + 1 < nkb) { load_kv(kb + 1, s ^ 1); cp_wait1(); }
        else              { cp_wait0(); }
        __syncthreads();

        const uint32_t kvb = sb + 32768 + s * 32768;

        // ---- S = Q K^T (split, 3 products) --------------------------------
        float sacc[8][4];
#pragma unroll
        for (int i = 0; i < 8; i++)
#pragma unroll
            for (int j = 0; j < 4; j++) sacc[i][j] = 0.f;

#pragma unroll
        for (int kk = 0; kk < 4; kk++) {
            uint32_t aqh[4], aql[4];
            uint32_t offA = SW128((warp * 16 + alr) * 128 + kk * 32 + alk * 16);
            ldsm4(aqh, sb + offA);
            ldsm4(aql, sb + 16384 + offA);
#pragma unroll
            for (int ni = 0; ni < 8; ni++) {
                uint32_t bh[2], bl[2];
                uint32_t offB = SW128((ni * 8 + bro) * 128 + kk * 32 + bk_ * 16);
                ldsm2(bh, kvb + offB);
                ldsm2(bl, kvb + 8192 + offB);
                mma16816(sacc[ni], aqh, bh);
                mma16816(sacc[ni], aqh, bl);
                mma16816(sacc[ni], aql, bh);
            }
        }

        // ---- causal mask (active only near the diagonal) ------------------
        if (kb >= 2 * qb) {
            int r0 = qb * 128 + warp * 16 + g, r1 = r0 + 8;
            int cb = kb * 64;
#pragma unroll
            for (int ni = 0; ni < 8; ni++) {
                int c = cb + ni * 8 + quad * 2;
                if (c     > r0) sacc[ni][0] = -1e30f;
                if (c + 1 > r0) sacc[ni][1] = -1e30f;
                if (c     > r1) sacc[ni][2] = -1e30f;
                if (c + 1 > r1) sacc[ni][3] = -1e30f;
            }
        }

        // ---- online softmax ----------------------------------------------
        float mx0 = -1e30f, mx1 = -1e30f;
#pragma unroll
        for (int ni = 0; ni < 8; ni++) {
            mx0 = fmaxf(mx0, fmaxf(sacc[ni][0], sacc[ni][1]));
            mx1 = fmaxf(mx1, fmaxf(sacc[ni][2], sacc[ni][3]));
        }
        mx0 = fmaxf(mx0, __shfl_xor_sync(0xffffffffu, mx0, 1));
        mx0 = fmaxf(mx0, __shfl_xor_sync(0xffffffffu, mx0, 2));
        mx1 = fmaxf(mx1, __shfl_xor_sync(0xffffffffu, mx1, 1));
        mx1 = fmaxf(mx1, __shfl_xor_sync(0xffffffffu, mx1, 2));
        float mn0 = fmaxf(mr0, mx0), mn1 = fmaxf(mr1, mx1);
        float c0 = __expf(mr0 - mn0), c1 = __expf(mr1 - mn1);
        mr0 = mn0; mr1 = mn1;

        float rs0 = 0.f, rs1 = 0.f;
#pragma unroll
        for (int ni = 0; ni < 8; ni++) {
            float p0 = __expf(sacc[ni][0] - mn0);
            float p1 = __expf(sacc[ni][1] - mn0);
            float p2 = __expf(sacc[ni][2] - mn1);
            float p3 = __expf(sacc[ni][3] - mn1);
            sacc[ni][0] = p0; sacc[ni][1] = p1; sacc[ni][2] = p2; sacc[ni][3] = p3;
            rs0 += p0 + p1; rs1 += p2 + p3;
        }
        rs0 += __shfl_xor_sync(0xffffffffu, rs0, 1);
        rs0 += __shfl_xor_sync(0xffffffffu, rs0, 2);
        rs1 += __shfl_xor_sync(0xffffffffu, rs1, 1);
        rs1 += __shfl_xor_sync(0xffffffffu, rs1, 2);
        lr0 = lr0 * c0 + rs0;
        lr1 = lr1 * c1 + rs1;
#pragma unroll
        for (int di = 0; di < 8; di++) {
            oacc[di][0] *= c0; oacc[di][1] *= c0;
            oacc[di][2] *= c1; oacc[di][3] *= c1;
        }

        // ---- O += P V (split P, split V, 3 products) ----------------------
#pragma unroll
        for (int ks = 0; ks < 4; ks++) {
            uint32_t aph[4], apl[4];
            float* s0 = sacc[2 * ks];
            float* s1 = sacc[2 * ks + 1];
            aph[0] = packbf(s0[0], s0[1]);
            aph[1] = packbf(s0[2], s0[3]);
            aph[2] = packbf(s1[0], s1[1]);
            aph[3] = packbf(s1[2], s1[3]);
            __nv_bfloat162 t;
            t = *(__nv_bfloat162*)&aph[0];
            apl[0] = packbf(s0[0] - __low2float(t), s0[1] - __high2float(t));
            t = *(__nv_bfloat162*)&aph[1];
            apl[1] = packbf(s0[2] - __low2float(t), s0[3] - __high2float(t));
            t = *(__nv_bfloat162*)&aph[2];
            apl[2] = packbf(s1[0] - __low2float(t), s1[1] - __high2float(t));
            t = *(__nv_bfloat162*)&aph[3];
            apl[3] = packbf(s1[2] - __low2float(t), s1[3] - __high2float(t));
#pragma unroll
            for (int di = 0; di < 8; di++) {
                uint32_t bvh[2], bvl[2];
                uint32_t offV = SW128((ks * 16 + alr) * 128 + di * 16);
                ldsm2t(bvh, kvb + 16384 + offV);
                ldsm2t(bvl, kvb + 24576 + offV);
                mma16816(oacc[di], aph, bvh);
                mma16816(oacc[di], apl, bvh);
                mma16816(oacc[di], aph, bvl);
            }
        }
        __syncthreads();   // stage s fully consumed before refill
    }

    // ---- epilogue: O /= l, split bf16 hi/lo, write y ----------------------
    float inv0 = 1.f / lr0, inv1 = 1.f / lr1;
    int r0 = qb * 128 + warp * 16 + g;
    size_t b0 = (size_t)r0 * C_DIM + h * DHEAD + quad * 2;
    size_t b1 = b0 + 8 * C_DIM;
#pragma unroll
    for (int di = 0; di < 8; di++) {
        float v00 = oacc[di][0] * inv0, v01 = oacc[di][1] * inv0;
        float v10 = oacc[di][2] * inv1, v11 = oacc[di][3] * inv1;
        __nv_bfloat162 h0 = __floats2bfloat162_rn(v00, v01);
        __nv_bfloat162 h1 = __floats2bfloat162_rn(v10, v11);
        __nv_bfloat162 l0 = __floats2bfloat162_rn(v00 - __low2float(h0),
                                                  v01 - __high2float(h0));
        __nv_bfloat162 l1 = __floats2bfloat162_rn(v10 - __low2float(h1),
                                                  v11 - __high2float(h1));
        *(__nv_bfloat162*)(Yh + b0 + di * 8) = h0;
        *(__nv_bfloat162*)(Yh + b1 + di * 8) = h1;
        *(__nv_bfloat162*)(Yl + b0 + di * 8) = l0;
        *(__nv_bfloat162*)(Yl + b1 + di * 8) = l1;
    }
}

// ---------------------------------------------------------------------------
extern "C" void kernel_launch(void* const* d_in, const int* in_sizes, int n_in,
                              void* d_out, int out_size)
{
    const float* x  = (const float*)d_in[0];
    const float* Wq = (const float*)d_in[1];
    const float* bq = (const float*)d_in[2];
    const float* Wk = (const float*)d_in[3];
    const float* bk = (const float*)d_in[4];
    const float* Wv = (const float*)d_in[5];
    const float* bv = (const float*)d_in[6];
    const float* Wp = (const float*)d_in[7];
    const float* bp = (const float*)d_in[8];
    float* out = (float*)d_out;

    __nv_bfloat16 *xh, *xl, *Wh, *Wl, *Wph, *Wpl, *yh, *yl, *qkvh, *qkvl;
    float *bqkv;
    cudaGetSymbolAddress((void**)&xh,    g_xh);
    cudaGetSymbolAddress((void**)&xl,    g_xl);
    cudaGetSymbolAddress((void**)&Wh,    g_Wh);
    cudaGetSymbolAddress((void**)&Wl,    g_Wl);
    cudaGetSymbolAddress((void**)&Wph,   g_Wph);
    cudaGetSymbolAddress((void**)&Wpl,   g_Wpl);
    cudaGetSymbolAddress((void**)&yh,    g_yh);
    cudaGetSymbolAddress((void**)&yl,    g_yl);
    cudaGetSymbolAddress((void**)&qkvh,  g_qkvh);
    cudaGetSymbolAddress((void**)&qkvl,  g_qkvl);
    cudaGetSymbolAddress((void**)&bqkv,  g_bqkv);

    cudaFuncSetAttribute(gemm_bf16s, cudaFuncAttributeMaxDynamicSharedMemorySize,
                         GEMM_SMEM);
    cudaFuncSetAttribute(attn_mma, cudaFuncAttributeMaxDynamicSharedMemorySize,
                         ATTN_SMEM);

    // 1: all weight splits in one launch
    split_w4<<<4096, 256>>>((const float4*)Wq, (const float4*)Wk,
                            (const float4*)Wv, (const float4*)Wp,
                            (__nv_bfloat162*)Wh,  (__nv_bfloat162*)Wl,
                            (__nv_bfloat162*)Wph, (__nv_bfloat162*)Wpl);
    // 2: x split
    split_kernel<<<4096, 256>>>((const float4*)x, (__nv_bfloat162*)xh,
                                (__nv_bfloat162*)xl, 1048576);
    // 3: bias concat
    concat_bias<<<3, 1024>>>(bq, bk, bv, bqkv);

    // 4: fused QKV projection -> split bf16 (q pre-scaled by 0.125)
    gemm_bf16s<<<dim3(QKV_DIM / 128, T_SEQ / 128), 256, GEMM_SMEM>>>(
        xh, xl, Wh, Wl, bqkv, nullptr, qkvh, qkvl, QKV_DIM, C_DIM, 1);

    // 5: attention -> split bf16 y   (slot ncu has been capturing)
    attn_mma<<<dim3(T_SEQ / 128, NHEAD), 256, ATTN_SMEM>>>(qkvh, qkvl, yh, yl);

    // 6: output projection -> fp32 out
    gemm_bf16s<<<dim3(C_DIM / 128, T_SEQ / 128), 256, GEMM_SMEM>>>(
        yh, yl, Wph, Wpl, bp, out, nullptr, nullptr, C_DIM, C_DIM, 0);
}

// round 6
// speedup vs baseline: 1.1091x; 1.1091x over previous
#include <cuda_runtime.h>
#include <cuda_bf16.h>
#include <cstdint>

#define T_SEQ 4096
#define C_DIM 1024
#define QKV_DIM 3072
#define NHEAD 16
#define DHEAD 64

// ---------------------------------------------------------------------------
// Static device scratch (no allocations allowed)
// ---------------------------------------------------------------------------
__device__ __nv_bfloat16 g_xh[T_SEQ * C_DIM];
__device__ __nv_bfloat16 g_xl[T_SEQ * C_DIM];
__device__ __nv_bfloat16 g_Wh[QKV_DIM * C_DIM];   // [Wq;Wk;Wv] hi
__device__ __nv_bfloat16 g_Wl[QKV_DIM * C_DIM];   // [Wq;Wk;Wv] lo
__device__ __nv_bfloat16 g_Wph[C_DIM * C_DIM];
__device__ __nv_bfloat16 g_Wpl[C_DIM * C_DIM];
__device__ float         g_bqkv[QKV_DIM];
__device__ __nv_bfloat16 g_qkvh[T_SEQ * QKV_DIM]; // fused q|k|v hi (q pre-scaled)
__device__ __nv_bfloat16 g_qkvl[T_SEQ * QKV_DIM]; // fused q|k|v lo
__device__ __nv_bfloat16 g_yh[T_SEQ * C_DIM];
__device__ __nv_bfloat16 g_yl[T_SEQ * C_DIM];

// q pre-scale: (1/sqrt(64)) * log2(e), so softmax uses ex2 directly
#define QSCALE 0.18033688011112042f

// ---------------------------------------------------------------------------
// PTX helpers (arch-agnostic; no tcgen05 — harness PTX target rejects it)
// ---------------------------------------------------------------------------
__device__ __forceinline__ uint32_t smem_u32(const void* p) {
    uint32_t a;
    asm("{ .reg .u64 t; cvta.to.shared.u64 t, %1; cvt.u32.u64 %0, t; }"
        : "=r"(a) : "l"(p));
    return a;
}
__device__ __forceinline__ void cp16(uint32_t dst, const void* src) {
    asm volatile("cp.async.cg.shared.global [%0], [%1], 16;" :: "r"(dst), "l"(src));
}
__device__ __forceinline__ void cp_commit() {
    asm volatile("cp.async.commit_group;" ::: "memory");
}
__device__ __forceinline__ void cp_wait0() {
    asm volatile("cp.async.wait_group 0;" ::: "memory");
}
__device__ __forceinline__ void cp_wait1() {
    asm volatile("cp.async.wait_group 1;" ::: "memory");
}
__device__ __forceinline__ void ldsm4(uint32_t* r, uint32_t addr) {
    asm volatile("ldmatrix.sync.aligned.m8n8.x4.shared.b16 {%0,%1,%2,%3}, [%4];"
                 : "=r"(r[0]), "=r"(r[1]), "=r"(r[2]), "=r"(r[3]) : "r"(addr));
}
__device__ __forceinline__ void ldsm2(uint32_t* r, uint32_t addr) {
    asm volatile("ldmatrix.sync.aligned.m8n8.x2.shared.b16 {%0,%1}, [%2];"
                 : "=r"(r[0]), "=r"(r[1]) : "r"(addr));
}
__device__ __forceinline__ void ldsm2t(uint32_t* r, uint32_t addr) {
    asm volatile("ldmatrix.sync.aligned.m8n8.x2.trans.shared.b16 {%0,%1}, [%2];"
                 : "=r"(r[0]), "=r"(r[1]) : "r"(addr));
}
__device__ __forceinline__ void mma16816(float* c, const uint32_t* a, const uint32_t* b) {
    asm volatile(
        "mma.sync.aligned.m16n8k16.row.col.f32.bf16.bf16.f32 "
        "{%0,%1,%2,%3}, {%4,%5,%6,%7}, {%8,%9}, {%0,%1,%2,%3};"
        : "+f"(c[0]), "+f"(c[1]), "+f"(c[2]), "+f"(c[3])
        : "r"(a[0]), "r"(a[1]), "r"(a[2]), "r"(a[3]), "r"(b[0]), "r"(b[1]));
}
__device__ __forceinline__ uint32_t packbf(float a, float b) {
    __nv_bfloat162 t = __floats2bfloat162_rn(a, b);
    return *(uint32_t*)&t;
}
__device__ __forceinline__ float ex2(float x) {
    float r;
    asm("ex2.approx.ftz.f32 %0, %1;" : "=f"(r) : "f"(x));
    return r;
}

// ---- mbarrier (sm_80/90 PTX, legal at compute_103) ------------------------
__device__ __forceinline__ void mbar_init(uint32_t a, uint32_t cnt) {
    asm volatile("mbarrier.init.shared.b64 [%0], %1;" :: "r"(a), "r"(cnt) : "memory");
}
__device__ __forceinline__ void mbar_arrive(uint32_t a) {
    asm volatile("{\n\t.reg .b64 t;\n\tmbarrier.arrive.shared.b64 t, [%0];\n\t}"
                 :: "r"(a) : "memory");
}
__device__ __forceinline__ void cp_arrive_noinc(uint32_t a) {
    asm volatile("cp.async.mbarrier.arrive.noinc.shared.b64 [%0];" :: "r"(a) : "memory");
}
__device__ __forceinline__ void mbar_wait(uint32_t a, uint32_t ph) {
    asm volatile(
        "{\n\t.reg .pred P;\n\t"
        "WL%=:\n\t"
        "mbarrier.try_wait.parity.shared.b64 P, [%0], %1;\n\t"
        "@!P bra WL%=;\n\t}"
        :: "r"(a), "r"(ph) : "memory");
}

#define SW128(o) ((o) ^ (((o) >> 3) & 0x70))

// ---------------------------------------------------------------------------
// Splits: fp32 -> bf16 hi + bf16 lo
// ---------------------------------------------------------------------------
__device__ __forceinline__ void split4(float4 v, __nv_bfloat162* h, __nv_bfloat162* l,
                                       int i)
{
    __nv_bfloat16 h0 = __float2bfloat16(v.x);
    __nv_bfloat16 h1 = __float2bfloat16(v.y);
    __nv_bfloat16 h2 = __float2bfloat16(v.z);
    __nv_bfloat16 h3 = __float2bfloat16(v.w);
    __nv_bfloat16 l0 = __float2bfloat16(v.x - __bfloat162float(h0));
    __nv_bfloat16 l1 = __float2bfloat16(v.y - __bfloat162float(h1));
    __nv_bfloat16 l2 = __float2bfloat16(v.z - __bfloat162float(h2));
    __nv_bfloat16 l3 = __float2bfloat16(v.w - __bfloat162float(h3));
    h[i * 2]     = __halves2bfloat162(h0, h1);
    h[i * 2 + 1] = __halves2bfloat162(h2, h3);
    l[i * 2]     = __halves2bfloat162(l0, l1);
    l[i * 2 + 1] = __halves2bfloat162(l2, l3);
}

__global__ void split_kernel(const float4* __restrict__ src,
                             __nv_bfloat162* __restrict__ h,
                             __nv_bfloat162* __restrict__ l, int n4)
{
    int i = blockIdx.x * blockDim.x + threadIdx.x;
    if (i >= n4) return;
    split4(src[i], h, l, i);
}

__global__ void split_w4(const float4* __restrict__ Wq, const float4* __restrict__ Wk,
                         const float4* __restrict__ Wv, const float4* __restrict__ Wp,
                         __nv_bfloat162* __restrict__ Wh, __nv_bfloat162* __restrict__ Wl,
                         __nv_bfloat162* __restrict__ Wph, __nv_bfloat162* __restrict__ Wpl)
{
    int w = blockIdx.x >> 10;
    int i = (blockIdx.x & 1023) * blockDim.x + threadIdx.x;
    const float4* src = (w == 0) ? Wq : (w == 1) ? Wk : (w == 2) ? Wv : Wp;
    __nv_bfloat162* h = (w == 3) ? Wph : Wh + (size_t)w * 524288;
    __nv_bfloat162* l = (w == 3) ? Wpl : Wl + (size_t)w * 524288;
    split4(src[i], h, l, i);
}

__global__ void concat_bias(const float* __restrict__ bq, const float* __restrict__ bk,
                            const float* __restrict__ bv, float* __restrict__ dst)
{
    int i = blockIdx.x * blockDim.x + threadIdx.x;
    if (i < 1024)      dst[i] = bq[i];
    else if (i < 2048) dst[i] = bk[i - 1024];
    else               dst[i] = bv[i - 2048];
}

// ---------------------------------------------------------------------------
// mma.sync split-bf16 GEMM (NT): C = (Ah+Al) @ (Bh+Bl)^T + bias
// 128x128 tile, BK=64, 256 threads, 2-stage cp.async (R4 config).
// mode 0: fp32 C.  mode 1: split-bf16 Ch/Cl, QSCALE on cols < C_DIM.
// ---------------------------------------------------------------------------
#define GEMM_SMEM (2 * 4 * 16384)

__global__ __launch_bounds__(256, 1)
void gemm_bf16s(const __nv_bfloat16* __restrict__ Ah, const __nv_bfloat16* __restrict__ Al,
                const __nv_bfloat16* __restrict__ Bh, const __nv_bfloat16* __restrict__ Bl,
                const float* __restrict__ bias, float* __restrict__ C,
                __nv_bfloat16* __restrict__ Ch, __nv_bfloat16* __restrict__ Cl,
                int N, int K, int mode)
{
    extern __shared__ char smem[];
    const int tid  = threadIdx.x;
    const int warp = tid >> 5;
    const int lane = tid & 31;
    const int wm   = warp >> 2;
    const int wn   = warp & 3;
    const int m0   = blockIdx.y * 128;
    const int n0   = blockIdx.x * 128;
    const uint32_t sbase = smem_u32(smem);
    const int NC = K / 64;

    const int lrow = tid >> 1;
    const int lj0  = (tid & 1) * 4;

    auto load_stage = [&](int c, int s) {
        const uint32_t sb = sbase + s * 65536;
        const size_t ka = (size_t)(m0 + lrow) * K + c * 64;
        const size_t kb = (size_t)(n0 + lrow) * K + c * 64;
#pragma unroll
        for (int j = lj0; j < lj0 + 4; j++) {
            uint32_t sw = SW128(lrow * 128 + j * 16);
            cp16(sb + sw,         Ah + ka + j * 8);
            cp16(sb + 16384 + sw, Al + ka + j * 8);
            cp16(sb + 32768 + sw, Bh + kb + j * 8);
            cp16(sb + 49152 + sw, Bl + kb + j * 8);
        }
        cp_commit();
    };

    float acc[4][4][4];
#pragma unroll
    for (int i = 0; i < 4; i++)
#pragma unroll
        for (int j = 0; j < 4; j++)
#pragma unroll
            for (int q = 0; q < 4; q++) acc[i][j][q] = 0.f;

    const int alr = lane & 15;
    const int alk = (lane >> 4) & 1;
    const int bro = lane & 7;
    const int bk_ = (lane >> 3) & 1;

    load_stage(0, 0);

    for (int c = 0; c < NC; c++) {
        const int s = c & 1;
        if (c + 1 < NC) { load_stage(c + 1, s ^ 1); cp_wait1(); }
        else            { cp_wait0(); }
        __syncthreads();

        const uint32_t sb = sbase + s * 65536;
#pragma unroll
        for (int kk = 0; kk < 4; kk++) {
            uint32_t ah[4][4], al4[4][4], bh[4][2], bl4[4][2];
#pragma unroll
            for (int mi = 0; mi < 4; mi++) {
                uint32_t off = SW128((wm * 64 + mi * 16 + alr) * 128 + kk * 32 + alk * 16);
                ldsm4(ah[mi],  sb + off);
                ldsm4(al4[mi], sb + 16384 + off);
            }
#pragma unroll
            for (int ni = 0; ni < 4; ni++) {
                uint32_t off = SW128((wn * 32 + ni * 8 + bro) * 128 + kk * 32 + bk_ * 16);
                ldsm2(bh[ni],  sb + 32768 + off);
                ldsm2(bl4[ni], sb + 49152 + off);
            }
#pragma unroll
            for (int mi = 0; mi < 4; mi++)
#pragma unroll
                for (int ni = 0; ni < 4; ni++) {
                    mma16816(acc[mi][ni], ah[mi],  bh[ni]);
                    mma16816(acc[mi][ni], ah[mi],  bl4[ni]);
                    mma16816(acc[mi][ni], al4[mi], bh[ni]);
                }
        }
        __syncthreads();
    }

    const int g   = lane >> 2;
    const int tig = lane & 3;
#pragma unroll
    for (int mi = 0; mi < 4; mi++) {
#pragma unroll
        for (int ni = 0; ni < 4; ni++) {
            int row = m0 + wm * 64 + mi * 16 + g;
            int col = n0 + wn * 32 + ni * 8 + tig * 2;
            float b0 = bias[col], b1 = bias[col + 1];
            if (mode == 0) {
                float2 v0 = {acc[mi][ni][0] + b0, acc[mi][ni][1] + b1};
                float2 v1 = {acc[mi][ni][2] + b0, acc[mi][ni][3] + b1};
                *(float2*)(C + (size_t)row * N + col)       = v0;
                *(float2*)(C + (size_t)(row + 8) * N + col) = v1;
            } else {
                float sc = (col < C_DIM) ? QSCALE : 1.0f;   // softmax+log2e on q
                float v00 = (acc[mi][ni][0] + b0) * sc;
                float v01 = (acc[mi][ni][1] + b1) * sc;
                float v10 = (acc[mi][ni][2] + b0) * sc;
                float v11 = (acc[mi][ni][3] + b1) * sc;
                __nv_bfloat162 h0 = __floats2bfloat162_rn(v00, v01);
                __nv_bfloat162 h1 = __floats2bfloat162_rn(v10, v11);
                __nv_bfloat162 l0 = __floats2bfloat162_rn(v00 - __low2float(h0),
                                                          v01 - __high2float(h0));
                __nv_bfloat162 l1 = __floats2bfloat162_rn(v10 - __low2float(h1),
                                                          v11 - __high2float(h1));
                *(__nv_bfloat162*)(Ch + (size_t)row * N + col)       = h0;
                *(__nv_bfloat162*)(Ch + (size_t)(row + 8) * N + col) = h1;
                *(__nv_bfloat162*)(Cl + (size_t)row * N + col)       = l0;
                *(__nv_bfloat162*)(Cl + (size_t)(row + 8) * N + col) = l1;
            }
        }
    }
}

// ---------------------------------------------------------------------------
// Flash attention via mma.sync, split-bf16, mbarrier pipeline (no
// __syncthreads in mainloop -> warps drift, softmax overlaps other warps'
// MMA). CTA = 128 q x 1 head, 8 warps, 256 threads. KV stage = 64 keys.
// SMEM: Q 32KB + 2 x 32KB stages + mbarriers = ~96KB; 2 CTAs/SM.
// ---------------------------------------------------------------------------
#define ATTN_MBAR  (32768 + 2 * 32768)
#define ATTN_SMEM  (ATTN_MBAR + 128)

__global__ __launch_bounds__(256, 2)
void attn_mma(const __nv_bfloat16* __restrict__ qkvh,
              const __nv_bfloat16* __restrict__ qkvl,
              __nv_bfloat16* __restrict__ Yh, __nv_bfloat16* __restrict__ Yl)
{
    extern __shared__ char smem[];
    const uint32_t sb = smem_u32(smem);
    const int qb   = gridDim.x - 1 - blockIdx.x;
    const int h    = blockIdx.y;
    const int tid  = threadIdx.x;
    const int warp = tid >> 5;
    const int lane = tid & 31;
    const int g    = lane >> 2;
    const int quad = lane & 3;
    const int nkb  = 2 * qb + 2;

    const uint32_t full0  = sb + ATTN_MBAR;
    const uint32_t full1  = sb + ATTN_MBAR + 8;
    const uint32_t empty0 = sb + ATTN_MBAR + 16;
    const uint32_t empty1 = sb + ATTN_MBAR + 24;

    if (tid == 0) {
        mbar_init(full0, 256); mbar_init(full1, 256);
        mbar_init(empty0, 256); mbar_init(empty1, 256);
    }
    __syncthreads();

    const int lrv = tid >> 2;
    const int ljv = (tid & 3) * 2;
    auto load_kv = [&](int kb, int s) {
        const uint32_t b = sb + 32768 + s * 32768;
        const size_t kbase = (size_t)(kb * 64 + lrv) * QKV_DIM + C_DIM + h * DHEAD;
        const size_t vbase = kbase + C_DIM;
#pragma unroll
        for (int j = ljv; j < ljv + 2; j++) {
            uint32_t sw = SW128(lrv * 128 + j * 16);
            cp16(b + sw,         qkvh + kbase + j * 8);
            cp16(b + 8192 + sw,  qkvl + kbase + j * 8);
            cp16(b + 16384 + sw, qkvh + vbase + j * 8);
            cp16(b + 24576 + sw, qkvl + vbase + j * 8);
        }
    };

    // prime: Q + stage 0 -> full0 ; stage 1 -> full1
    {
        const int lr  = tid >> 1;
        const int lj0 = (tid & 1) * 4;
        const size_t base = (size_t)(qb * 128 + lr) * QKV_DIM + h * DHEAD;
#pragma unroll
        for (int j = lj0; j < lj0 + 4; j++) {
            uint32_t sw = SW128(lr * 128 + j * 16);
            cp16(sb + sw,         qkvh + base + j * 8);
            cp16(sb + 16384 + sw, qkvl + base + j * 8);
        }
    }
    load_kv(0, 0);
    cp_arrive_noinc(full0);            // Q + stage0 complete -> full0
    if (nkb > 1) { load_kv(1, 1); }
    cp_arrive_noinc(full1);            // (even if nkb==1, harmless arrival)

    float oacc[8][4];
#pragma unroll
    for (int i = 0; i < 8; i++)
#pragma unroll
        for (int j = 0; j < 4; j++) oacc[i][j] = 0.f;
    float mr0 = -1e30f, mr1 = -1e30f, lr0 = 0.f, lr1 = 0.f;

    const int alr = lane & 15;
    const int alk = (lane >> 4) & 1;
    const int bro = lane & 7;
    const int bk_ = (lane >> 3) & 1;

    uint32_t fph0 = 0, fph1 = 0, eph0 = 0, eph1 = 0;

    for (int kb = 0; kb < nkb; kb++) {
        const int s = kb & 1;
        const uint32_t kvb = sb + 32768 + s * 32768;

        // wait stage s full
        if (s == 0) { mbar_wait(full0, fph0); fph0 ^= 1; }
        else        { mbar_wait(full1, fph1); fph1 ^= 1; }

        // ---- S = Q K^T (split, 3 products) --------------------------------
        float sacc[8][4];
#pragma unroll
        for (int i = 0; i < 8; i++)
#pragma unroll
            for (int j = 0; j < 4; j++) sacc[i][j] = 0.f;

#pragma unroll
        for (int kk = 0; kk < 4; kk++) {
            uint32_t aqh[4], aql[4];
            uint32_t offA = SW128((warp * 16 + alr) * 128 + kk * 32 + alk * 16);
            ldsm4(aqh, sb + offA);
            ldsm4(aql, sb + 16384 + offA);
#pragma unroll
            for (int ni = 0; ni < 8; ni++) {
                uint32_t bh[2], bl[2];
                uint32_t offB = SW128((ni * 8 + bro) * 128 + kk * 32 + bk_ * 16);
                ldsm2(bh, kvb + offB);
                ldsm2(bl, kvb + 8192 + offB);
                mma16816(sacc[ni], aqh, bh);
                mma16816(sacc[ni], aqh, bl);
                mma16816(sacc[ni], aql, bh);
            }
        }

        // ---- producer duty: refill the OTHER stage for iter kb+1 ----------
        // (placed here so the empty-wait overlaps this warp's upcoming
        //  softmax with other warps' MMA; stage s^1 was last read at kb-1)
        if (kb >= 1 && kb + 1 < nkb) {
            if (s == 0) { mbar_wait(empty1, eph1); eph1 ^= 1;
                          load_kv(kb + 1, 1); cp_arrive_noinc(full1); }
            else        { mbar_wait(empty0, eph0); eph0 ^= 1;
                          load_kv(kb + 1, 0); cp_arrive_noinc(full0); }
        }

        // ---- causal mask (active only near the diagonal) ------------------
        if (kb >= 2 * qb) {
            int r0 = qb * 128 + warp * 16 + g, r1 = r0 + 8;
            int cb = kb * 64;
#pragma unroll
            for (int ni = 0; ni < 8; ni++) {
                int c = cb + ni * 8 + quad * 2;
                if (c     > r0) sacc[ni][0] = -1e30f;
                if (c + 1 > r0) sacc[ni][1] = -1e30f;
                if (c     > r1) sacc[ni][2] = -1e30f;
                if (c + 1 > r1) sacc[ni][3] = -1e30f;
            }
        }

        // ---- online softmax (base-2 domain; q pre-scaled by log2e) --------
        float mx0 = -1e30f, mx1 = -1e30f;
#pragma unroll
        for (int ni = 0; ni < 8; ni++) {
            mx0 = fmaxf(mx0, fmaxf(sacc[ni][0], sacc[ni][1]));
            mx1 = fmaxf(mx1, fmaxf(sacc[ni][2], sacc[ni][3]));
        }
        mx0 = fmaxf(mx0, __shfl_xor_sync(0xffffffffu, mx0, 1));
        mx0 = fmaxf(mx0, __shfl_xor_sync(0xffffffffu, mx0, 2));
        mx1 = fmaxf(mx1, __shfl_xor_sync(0xffffffffu, mx1, 1));
        mx1 = fmaxf(mx1, __shfl_xor_sync(0xffffffffu, mx1, 2));
        float mn0 = fmaxf(mr0, mx0), mn1 = fmaxf(mr1, mx1);
        float c0 = ex2(mr0 - mn0), c1 = ex2(mr1 - mn1);
        mr0 = mn0; mr1 = mn1;

        float rs0 = 0.f, rs1 = 0.f;
#pragma unroll
        for (int ni = 0; ni < 8; ni++) {
            float p0 = ex2(sacc[ni][0] - mn0);
            float p1 = ex2(sacc[ni][1] - mn0);
            float p2 = ex2(sacc[ni][2] - mn1);
            float p3 = ex2(sacc[ni][3] - mn1);
            sacc[ni][0] = p0; sacc[ni][1] = p1; sacc[ni][2] = p2; sacc[ni][3] = p3;
            rs0 += p0 + p1; rs1 += p2 + p3;
        }
        rs0 += __shfl_xor_sync(0xffffffffu, rs0, 1);
        rs0 += __shfl_xor_sync(0xffffffffu, rs0, 2);
        rs1 += __shfl_xor_sync(0xffffffffu, rs1, 1);
        rs1 += __shfl_xor_sync(0xffffffffu, rs1, 2);
        lr0 = lr0 * c0 + rs0;
        lr1 = lr1 * c1 + rs1;
#pragma unroll
        for (int di = 0; di < 8; di++) {
            oacc[di][0] *= c0; oacc[di][1] *= c0;
            oacc[di][2] *= c1; oacc[di][3] *= c1;
        }

        // ---- O += P V (split P, split V, 3 products) ----------------------
#pragma unroll
        for (int ks = 0; ks < 4; ks++) {
            uint32_t aph[4], apl[4];
            float* s0 = sacc[2 * ks];
            float* s1 = sacc[2 * ks + 1];
            aph[0] = packbf(s0[0], s0[1]);
            aph[1] = packbf(s0[2], s0[3]);
            aph[2] = packbf(s1[0], s1[1]);
            aph[3] = packbf(s1[2], s1[3]);
            __nv_bfloat162 t;
            t = *(__nv_bfloat162*)&aph[0];
            apl[0] = packbf(s0[0] - __low2float(t), s0[1] - __high2float(t));
            t = *(__nv_bfloat162*)&aph[1];
            apl[1] = packbf(s0[2] - __low2float(t), s0[3] - __high2float(t));
            t = *(__nv_bfloat162*)&aph[2];
            apl[2] = packbf(s1[0] - __low2float(t), s1[1] - __high2float(t));
            t = *(__nv_bfloat162*)&aph[3];
            apl[3] = packbf(s1[2] - __low2float(t), s1[3] - __high2float(t));
#pragma unroll
            for (int di = 0; di < 8; di++) {
                uint32_t bvh[2], bvl[2];
                uint32_t offV = SW128((ks * 16 + alr) * 128 + di * 16);
                ldsm2t(bvh, kvb + 16384 + offV);
                ldsm2t(bvl, kvb + 24576 + offV);
                mma16816(oacc[di], aph, bvh);
                mma16816(oacc[di], apl, bvh);
                mma16816(oacc[di], aph, bvl);
            }
        }

        // done reading stage s
        if (s == 0) mbar_arrive(empty0);
        else        mbar_arrive(empty1);
    }

    // ---- epilogue: O /= l, split bf16 hi/lo, write y ----------------------
    float inv0 = 1.f / lr0, inv1 = 1.f / lr1;
    int r0 = qb * 128 + warp * 16 + g;
    size_t b0 = (size_t)r0 * C_DIM + h * DHEAD + quad * 2;
    size_t b1 = b0 + 8 * C_DIM;
#pragma unroll
    for (int di = 0; di < 8; di++) {
        float v00 = oacc[di][0] * inv0, v01 = oacc[di][1] * inv0;
        float v10 = oacc[di][2] * inv1, v11 = oacc[di][3] * inv1;
        __nv_bfloat162 h0 = __floats2bfloat162_rn(v00, v01);
        __nv_bfloat162 h1 = __floats2bfloat162_rn(v10, v11);
        __nv_bfloat162 l0 = __floats2bfloat162_rn(v00 - __low2float(h0),
                                                  v01 - __high2float(h0));
        __nv_bfloat162 l1 = __floats2bfloat162_rn(v10 - __low2float(h1),
                                                  v11 - __high2float(h1));
        *(__nv_bfloat162*)(Yh + b0 + di * 8) = h0;
        *(__nv_bfloat162*)(Yh + b1 + di * 8) = h1;
        *(__nv_bfloat162*)(Yl + b0 + di * 8) = l0;
        *(__nv_bfloat162*)(Yl + b1 + di * 8) = l1;
    }
}

// ---------------------------------------------------------------------------
extern "C" void kernel_launch(void* const* d_in, const int* in_sizes, int n_in,
                              void* d_out, int out_size)
{
    const float* x  = (const float*)d_in[0];
    const float* Wq = (const float*)d_in[1];
    const float* bq = (const float*)d_in[2];
    const float* Wk = (const float*)d_in[3];
    const float* bk = (const float*)d_in[4];
    const float* Wv = (const float*)d_in[5];
    const float* bv = (const float*)d_in[6];
    const float* Wp = (const float*)d_in[7];
    const float* bp = (const float*)d_in[8];
    float* out = (float*)d_out;

    __nv_bfloat16 *xh, *xl, *Wh, *Wl, *Wph, *Wpl, *yh, *yl, *qkvh, *qkvl;
    float *bqkv;
    cudaGetSymbolAddress((void**)&xh,    g_xh);
    cudaGetSymbolAddress((void**)&xl,    g_xl);
    cudaGetSymbolAddress((void**)&Wh,    g_Wh);
    cudaGetSymbolAddress((void**)&Wl,    g_Wl);
    cudaGetSymbolAddress((void**)&Wph,   g_Wph);
    cudaGetSymbolAddress((void**)&Wpl,   g_Wpl);
    cudaGetSymbolAddress((void**)&yh,    g_yh);
    cudaGetSymbolAddress((void**)&yl,    g_yl);
    cudaGetSymbolAddress((void**)&qkvh,  g_qkvh);
    cudaGetSymbolAddress((void**)&qkvl,  g_qkvl);
    cudaGetSymbolAddress((void**)&bqkv,  g_bqkv);

    cudaFuncSetAttribute(gemm_bf16s, cudaFuncAttributeMaxDynamicSharedMemorySize,
                         GEMM_SMEM);
    cudaFuncSetAttribute(attn_mma, cudaFuncAttributeMaxDynamicSharedMemorySize,
                         ATTN_SMEM);

    split_w4<<<4096, 256>>>((const float4*)Wq, (const float4*)Wk,
                            (const float4*)Wv, (const float4*)Wp,
                            (__nv_bfloat162*)Wh,  (__nv_bfloat162*)Wl,
                            (__nv_bfloat162*)Wph, (__nv_bfloat162*)Wpl);
    split_kernel<<<4096, 256>>>((const float4*)x, (__nv_bfloat162*)xh,
                                (__nv_bfloat162*)xl, 1048576);
    concat_bias<<<3, 1024>>>(bq, bk, bv, bqkv);

    gemm_bf16s<<<dim3(QKV_DIM / 128, T_SEQ / 128), 256, GEMM_SMEM>>>(
        xh, xl, Wh, Wl, bqkv, nullptr, qkvh, qkvl, QKV_DIM, C_DIM, 1);

    attn_mma<<<dim3(T_SEQ / 128, NHEAD), 256, ATTN_SMEM>>>(qkvh, qkvl, yh, yl);

    gemm_bf16s<<<dim3(C_DIM / 128, T_SEQ / 128), 256, GEMM_SMEM>>>(
        yh, yl, Wph, Wpl, bp, out, nullptr, nullptr, C_DIM, C_DIM, 0);
}